// round 15
// baseline (speedup 1.0000x reference)
#include <cuda_runtime.h>

#define NN 100000
#define EE 3200000
#define NG 100
#define NPER 1000
#define EPG 32000
#define KTOP 800
#define NGC 50                    // graphs per chunk
#define NNC (NGC * NPER)          // nodes per chunk

// ---------------- global scratch (static; no cudaMalloc) ----------------
__device__ int    g_off[NN + 1];
__device__ int    g_csr[EE];
__device__ float  g_dis[NN];
__device__ float  g_dis2[NN];
__device__ float  g_score[NN];
__device__ float  g_f[NN];             // score * dis2 (0 for masked)
__device__ float  g_p[NN];             // h . w_rel
__device__ float  g_hr[NN];            // h . w_root
__device__ float4 g_xw[NN * 4];        // x @ W1 (NO dis) [N,16]
__device__ float4 g_h4[NN * 4];        // conv1 output  [N,16]
__device__ float4 g_gg[NN * 4];        // conv2 agg (pre-W2) [N,16]

// ---- thread-per-node scalar gather over one CSR bucket, table in SMEM ----
__device__ __forceinline__ float gather_sum_smem(const float* __restrict__ tab,
                                                 int beg, int end, int nbase) {
    float a0 = 0.f, a1 = 0.f, a2 = 0.f, a3 = 0.f;
    int i = beg;
    for (; i < end && (i & 3); i++) a0 += tab[__ldg(&g_csr[i]) - nbase];
    int n4 = (end - i) >> 2;
    const int4* c4 = (const int4*)&g_csr[i];
    for (int k = 0; k < n4; k++) {
        int4 u = __ldg(&c4[k]);
        a0 += tab[u.x - nbase];
        a1 += tab[u.y - nbase];
        a2 += tab[u.z - nbase];
        a3 += tab[u.w - nbase];
    }
    for (i += n4 << 2; i < end; i++) a0 += tab[__ldg(&g_csr[i]) - nbase];
    return (a0 + a1) + (a2 + a3);
}

// ============ CSR build: register-cached ranks; one chunk of graphs ============
__global__ void __launch_bounds__(1024) k_build(const int* __restrict__ src,
                                                const int* __restrict__ dst,
                                                int gbase) {
    __shared__ int sdeg[1024];
    __shared__ int soff[1024];
    int g = gbase + blockIdx.x, t = threadIdx.x;
    int ebase = g * EPG, nbase = g * NPER;
    sdeg[t] = 0;
    __syncthreads();
    unsigned pk[32];   // (rank<<16) | local_dst
#pragma unroll
    for (int k = 0; k < 32; k++) {
        int e = t + (k << 10);
        if (e < EPG) {
            int d = dst[ebase + e] - nbase;
            unsigned r = atomicAdd(&sdeg[d], 1);
            pk[k] = (r << 16) | (unsigned)d;
        }
    }
    __syncthreads();
    int v = sdeg[t];
    soff[t] = v;
    __syncthreads();
    for (int d = 1; d < 1024; d <<= 1) {
        int cur = soff[t];
        int add = (t >= d) ? soff[t - d] : 0;
        __syncthreads();
        soff[t] = cur + add;
        __syncthreads();
    }
    int excl = soff[t] - v;
    if (t < NPER) {
        g_off[nbase + t] = ebase + excl;
        g_dis[nbase + t] = rsqrtf((float)(v + 1));
    }
    if (g == NG - 1 && t == 0) g_off[NN] = EE;
    sdeg[t] = excl;
    __syncthreads();
#pragma unroll
    for (int k = 0; k < 32; k++) {
        int e = t + (k << 10);
        if (e < EPG) {
            unsigned p = pk[k];
            int d = p & 0xFFFFu;
            int r = (int)(p >> 16);
            g_csr[ebase + sdeg[d] + r] = src[ebase + e];
        }
    }
}

// ============ GEMM1: xw = x @ W1, node range [nbase0, nend) ============
__global__ void k_gemm1(const float* __restrict__ x, const float* __restrict__ W1,
                        int nbase0, int nend) {
    __shared__ float xs[64 * 129];
    __shared__ float ws[128 * 16];
    int tid = threadIdx.x;
    int v0 = nbase0 + blockIdx.x * 64;
    for (int i = tid; i < 2048; i += 256) ws[i] = W1[i];
    const float4* x4 = (const float4*)x;
    for (int i = tid; i < 64 * 32; i += 256) {
        int r = i >> 5, c = i & 31;
        int v = v0 + r;
        float4 val = (v < nend) ? x4[(size_t)v * 32 + c] : make_float4(0.f, 0.f, 0.f, 0.f);
        float* p = &xs[r * 129 + c * 4];
        p[0] = val.x; p[1] = val.y; p[2] = val.z; p[3] = val.w;
    }
    __syncthreads();
    int n = tid & 63;
    int jg = tid >> 6;
    float4 acc = make_float4(0.f, 0.f, 0.f, 0.f);
    const float4* ws4 = (const float4*)ws;
    const float* xr = &xs[n * 129];
#pragma unroll 8
    for (int k = 0; k < 128; k++) {
        float xv = xr[k];
        float4 w = ws4[k * 4 + jg];
        acc.x += xv * w.x; acc.y += xv * w.y; acc.z += xv * w.z; acc.w += xv * w.w;
    }
    int v = v0 + n;
    if (v < nend) g_xw[v * 4 + jg] = acc;
}

// ============ conv1: scalar 16-lane SMEM gather; tile = xw*dis at load ============
__global__ void __launch_bounds__(512) k_conv1(const float* __restrict__ b1,
                                               const float* __restrict__ wrel,
                                               const float* __restrict__ wroot,
                                               int gbase) {
    extern __shared__ float tile[];   // [1000][16] = xw * dis
    int g = gbase + (blockIdx.x >> 2);
    int quarter = blockIdx.x & 3;
    int nbase = g * NPER;
    int tid = threadIdx.x;
    const float4* src4 = (const float4*)&g_xw[nbase * 4];
    float4* t4 = (float4*)tile;
    for (int i = tid; i < NPER * 4; i += 512) {
        int vl = i >> 2;
        float d = g_dis[nbase + vl];
        float4 val = src4[i];
        t4[i] = make_float4(val.x * d, val.y * d, val.z * d, val.w * d);
    }
    __syncthreads();
    int wid = tid >> 5, lane = tid & 31;
    int hh = lane >> 4, f = lane & 15;
    float bf = __ldg(&b1[f]);
    float wrf = __ldg(&wrel[f]);
    float wof = __ldg(&wroot[f]);
    int vbeg = quarter * 250, vend = vbeg + 250;
    for (int vl = vbeg + wid; vl < vend; vl += 16) {
        int v = nbase + vl;
        int beg = g_off[v], end = g_off[v + 1];
        float acc = 0.f;
        for (int i = beg + hh; i < end; i += 2) {
            int u = __ldg(&g_csr[i]) - nbase;
            acc += tile[u * 16 + f];
        }
        acc += __shfl_xor_sync(0xffffffffu, acc, 16);
        float d = g_dis[v];
        float hv = fmaxf(fmaf(d, acc + tile[vl * 16 + f], bf), 0.f);
        if (hh == 0) ((float*)g_h4)[v * 16 + f] = hv;
        float pp = hv * wrf;
        float rr = hv * wof;
#pragma unroll
        for (int m = 1; m < 16; m <<= 1) {
            pp += __shfl_xor_sync(0xffffffffu, pp, m);
            rr += __shfl_xor_sync(0xffffffffu, rr, m);
        }
        if (lane == 0) { g_p[v] = pp; g_hr[v] = rr; }
    }
}

// ============ score: thread-per-node, p-tile in SMEM; 2 blocks/graph x 512 ============
__global__ void __launch_bounds__(512) k_score(const float* __restrict__ brel, int gbase) {
    __shared__ float p_s[NPER];
    int g = gbase + (blockIdx.x >> 1);
    int half = blockIdx.x & 1;
    int nbase = g * NPER;
    int t = threadIdx.x;
    for (int i = t; i < NPER; i += 512) p_s[i] = g_p[nbase + i];
    __syncthreads();
    int vl = half * 500 + t;
    if (t < 500) {
        int v = nbase + vl;
        float s = gather_sum_smem(p_s, g_off[v], g_off[v + 1], nbase);
        g_score[v] = tanhf(s + g_hr[v] + __ldg(brel));
    }
}

// ============ top-K: hybrid bitonic + thread-per-node deg2 ============
__global__ void __launch_bounds__(1024) k_topk(int gbase) {
    __shared__ unsigned long long keys[1024];
    __shared__ float smask[NPER];
    int g = gbase + blockIdx.x, t = threadIdx.x;
    int nbase = g * NPER;
    if (t < NPER) {
        unsigned u = __float_as_uint(g_score[nbase + t]);
        u = (u & 0x80000000u) ? ~u : (u | 0x80000000u);
        keys[t] = ((unsigned long long)u << 32) | (unsigned)(~t);  // ties: lower idx wins
    } else {
        keys[t] = 0ull;
    }
    __syncthreads();
    for (int k = 2; k <= 1024; k <<= 1) {
        for (int j = k >> 1; j >= 32; j >>= 1) {
            int ixj = t ^ j;
            if (ixj > t) {
                unsigned long long a = keys[t], b = keys[ixj];
                bool up = ((t & k) == 0);
                if ((a > b) == up) { keys[t] = b; keys[ixj] = a; }
            }
            __syncthreads();
        }
        unsigned long long v = keys[t];
        bool up = ((t & k) == 0);
        int jstart = (k >> 1 < 16) ? (k >> 1) : 16;
        for (int j = jstart; j > 0; j >>= 1) {
            unsigned long long o = __shfl_xor_sync(0xffffffffu, v, j);
            bool lower = ((t & j) == 0);
            bool keepmin = (lower == up);
            unsigned long long mn = (v < o) ? v : o;
            unsigned long long mx = (v < o) ? o : v;
            v = keepmin ? mn : mx;
        }
        keys[t] = v;
        __syncthreads();
    }
    if (t >= (1024 - NPER)) {
        unsigned idx = ~(unsigned)(keys[t] & 0xFFFFFFFFull);
        smask[idx] = (t >= 1024 - KTOP) ? 1.0f : 0.0f;
    }
    __syncthreads();
    if (t < NPER) {
        int v = nbase + t;
        float s = gather_sum_smem(smask, g_off[v], g_off[v + 1], nbase);
        float mv = smask[t];
        float d2 = (mv > 0.f) ? rsqrtf(mv + s) : 0.f;
        g_dis2[v] = d2;
        g_f[v] = g_score[v] * d2;
    }
}

// ============ conv2: 64KB c2-tile, float4 gather ============
__global__ void __launch_bounds__(512) k_conv2(int gbase) {
    extern __shared__ float c2[];   // [1000*16]
    int g = gbase + (blockIdx.x >> 2);
    int quarter = blockIdx.x & 3;
    int nbase = g * NPER;
    int t = threadIdx.x;
    const float4* h4 = (const float4*)&g_h4[nbase * 4];
    float4* c24 = (float4*)c2;
    for (int i = t; i < NPER * 4; i += 512) {
        int vl = i >> 2;
        float f = __ldg(&g_f[nbase + vl]);
        float4 h = h4[i];
        c24[i] = make_float4(h.x * f, h.y * f, h.z * f, h.w * f);
    }
    __syncthreads();
    int wid = t >> 5, lane = t & 31;
    int sub = lane >> 2, c = lane & 3;
    int vbeg = quarter * 250, vend = vbeg + 250;
    for (int vl = vbeg + wid; vl < vend; vl += 16) {
        int v = nbase + vl;
        float d2 = g_dis2[v];
        if (d2 == 0.f) continue;
        int beg = g_off[v], end = g_off[v + 1];
        float4 acc = make_float4(0.f, 0.f, 0.f, 0.f);
        for (int i = beg + sub; i < end; i += 8) {
            int u = __ldg(&g_csr[i]) - nbase;
            float4 tt = c24[u * 4 + c];
            acc.x += tt.x; acc.y += tt.y; acc.z += tt.z; acc.w += tt.w;
        }
#pragma unroll
        for (int m = 4; m < 32; m <<= 1) {
            acc.x += __shfl_xor_sync(0xffffffffu, acc.x, m);
            acc.y += __shfl_xor_sync(0xffffffffu, acc.y, m);
            acc.z += __shfl_xor_sync(0xffffffffu, acc.z, m);
            acc.w += __shfl_xor_sync(0xffffffffu, acc.w, m);
        }
        if (sub == 0) {
            float4 cv = c24[vl * 4 + c];
            g_gg[v * 4 + c] = make_float4(d2 * (acc.x + cv.x), d2 * (acc.y + cv.y),
                                          d2 * (acc.z + cv.z), d2 * (acc.w + cv.w));
        }
    }
}

// ============ fused GEMM2(16->256) + relu + masked mean pool (W2 in regs) ============
__global__ void k_pool(const float* __restrict__ W2, const float* __restrict__ b2,
                       float* __restrict__ out, int gbase) {
    __shared__ float gs[16][16];
    __shared__ float ms[16];
    int t = threadIdx.x;
    int gi = gbase + (blockIdx.x >> 3);
    int part = blockIdx.x & 7;
    int node0 = gi * NPER + part * 125;
    float w0[16], w1[16];
#pragma unroll
    for (int m = 0; m < 16; m++) {
        w0[m] = __ldg(&W2[m * 256 + t]);
        w1[m] = __ldg(&W2[m * 256 + t + 128]);
    }
    float bb0 = __ldg(&b2[t]), bb1 = __ldg(&b2[t + 128]);
    float acc0 = 0.f, acc1 = 0.f;
    const float* gflat = (const float*)g_gg;
    for (int base = 0; base < 125; base += 16) {
        int ns = min(16, 125 - base);
        for (int i = t; i < ns * 16; i += 128)
            ((float*)gs)[i] = gflat[(node0 + base) * 16 + i];
        if (t < ns) ms[t] = g_dis2[node0 + base + t];
        __syncthreads();
        for (int q = 0; q < ns; q++) {
            if (ms[q] != 0.f) {
                float s0 = bb0, s1 = bb1;
#pragma unroll
                for (int m = 0; m < 16; m++) {
                    float gv = gs[q][m];
                    s0 = fmaf(gv, w0[m], s0);
                    s1 = fmaf(gv, w1[m], s1);
                }
                acc0 += fmaxf(s0, 0.f);
                acc1 += fmaxf(s1, 0.f);
            }
        }
        __syncthreads();
    }
    const float inv = 1.0f / (float)KTOP;
    atomicAdd(&out[gi * 256 + t], acc0 * inv);
    atomicAdd(&out[gi * 256 + t + 128], acc1 * inv);
}

// ============ launch: two independent 50-graph pipelines on two streams ============
extern "C" void kernel_launch(void* const* d_in, const int* in_sizes, int n_in,
                              void* d_out, int out_size) {
    const float* x     = (const float*)d_in[0];
    const int*   ei    = (const int*)d_in[1];
    const float* W1    = (const float*)d_in[3];
    const float* b1    = (const float*)d_in[4];
    const float* wrel  = (const float*)d_in[5];
    const float* brel  = (const float*)d_in[6];
    const float* wroot = (const float*)d_in[7];
    const float* W2    = (const float*)d_in[8];
    const float* b2    = (const float*)d_in[9];
    float* out = (float*)d_out;

    const int* src = ei;
    const int* dst = ei + EE;

    static cudaStream_t s2 = nullptr;
    static cudaEvent_t eFork = nullptr, eJoin = nullptr;
    if (s2 == nullptr) {
        cudaStreamCreateWithFlags(&s2, cudaStreamNonBlocking);
        cudaEventCreateWithFlags(&eFork, cudaEventDisableTiming);
        cudaEventCreateWithFlags(&eJoin, cudaEventDisableTiming);
        const int TILE_SMEM = NPER * 16 * 4;   // 64000
        cudaFuncSetAttribute(k_conv1, cudaFuncAttributeMaxDynamicSharedMemorySize, TILE_SMEM);
        cudaFuncSetAttribute(k_conv2, cudaFuncAttributeMaxDynamicSharedMemorySize, TILE_SMEM);
    }
    const int TILE_SMEM = NPER * 16 * 4;
    const int GEMM_BLKS = (NNC + 63) / 64;   // 782

    cudaMemsetAsync(d_out, 0, (size_t)out_size * sizeof(float), 0);

    // fork chunk B onto s2
    cudaEventRecord(eFork, 0);
    cudaStreamWaitEvent(s2, eFork, 0);

    // ---- chunk A (graphs 0..49) on the main stream ----
    k_gemm1<<<GEMM_BLKS, 256>>>(x, W1, 0, NNC);
    k_build<<<NGC, 1024>>>(src, dst, 0);
    k_conv1<<<NGC * 4, 512, TILE_SMEM>>>(b1, wrel, wroot, 0);
    k_score<<<NGC * 2, 512>>>(brel, 0);
    k_topk<<<NGC, 1024>>>(0);
    k_conv2<<<NGC * 4, 512, TILE_SMEM>>>(0);
    k_pool<<<NGC * 8, 128>>>(W2, b2, out, 0);

    // ---- chunk B (graphs 50..99) on s2 ----
    k_build<<<NGC, 1024, 0, s2>>>(src, dst, NGC);
    k_gemm1<<<GEMM_BLKS, 256, 0, s2>>>(x, W1, NNC, 2 * NNC);
    k_conv1<<<NGC * 4, 512, TILE_SMEM, s2>>>(b1, wrel, wroot, NGC);
    k_score<<<NGC * 2, 512, 0, s2>>>(brel, NGC);
    k_topk<<<NGC, 1024, 0, s2>>>(NGC);
    k_conv2<<<NGC * 4, 512, TILE_SMEM, s2>>>(NGC);
    k_pool<<<NGC * 8, 128, 0, s2>>>(W2, b2, out, NGC);

    // join B back into the main stream
    cudaEventRecord(eJoin, s2);
    cudaStreamWaitEvent(0, eJoin, 0);
}

// round 16
// speedup vs baseline: 1.0438x; 1.0438x over previous
#include <cuda_runtime.h>

#define NN 100000
#define EE 3200000
#define NG 100
#define NPER 1000
#define EPG 32000
#define KTOP 800

// ---------------- global scratch (static; no cudaMalloc) ----------------
__device__ int    g_off[NN + 1];
__device__ int    g_csr[EE];
__device__ float  g_dis[NN];
__device__ float  g_dis2[NN];
__device__ float  g_f[NN];             // score * dis2 (0 for masked)
__device__ float  g_p[NN];             // h . w_rel
__device__ float  g_hr[NN];            // h . w_root
__device__ float4 g_xw[NN * 4];        // x @ W1 (NO dis) [N,16]
__device__ float4 g_h4[NN * 4];        // conv1 output  [N,16]
__device__ float4 g_gg[NN * 4];        // conv2 agg (pre-W2) [N,16]

// ---- thread-per-node scalar gather over one CSR bucket, table in SMEM ----
__device__ __forceinline__ float gather_sum_smem(const float* __restrict__ tab,
                                                 int beg, int end, int nbase) {
    float a0 = 0.f, a1 = 0.f, a2 = 0.f, a3 = 0.f;
    int i = beg;
    for (; i < end && (i & 3); i++) a0 += tab[__ldg(&g_csr[i]) - nbase];
    int n4 = (end - i) >> 2;
    const int4* c4 = (const int4*)&g_csr[i];
    for (int k = 0; k < n4; k++) {
        int4 u = __ldg(&c4[k]);
        a0 += tab[u.x - nbase];
        a1 += tab[u.y - nbase];
        a2 += tab[u.z - nbase];
        a3 += tab[u.w - nbase];
    }
    for (i += n4 << 2; i < end; i++) a0 += tab[__ldg(&g_csr[i]) - nbase];
    return (a0 + a1) + (a2 + a3);
}

// ============ CSR build: register-cached ranks (no g_rank round-trip) ============
__global__ void __launch_bounds__(1024) k_build(const int* __restrict__ src,
                                                const int* __restrict__ dst) {
    __shared__ int sdeg[1024];
    __shared__ int soff[1024];
    int g = blockIdx.x, t = threadIdx.x;
    int ebase = g * EPG, nbase = g * NPER;
    sdeg[t] = 0;
    __syncthreads();
    unsigned pk[32];   // (rank<<16) | local_dst
#pragma unroll
    for (int k = 0; k < 32; k++) {
        int e = t + (k << 10);
        if (e < EPG) {
            int d = dst[ebase + e] - nbase;
            unsigned r = atomicAdd(&sdeg[d], 1);
            pk[k] = (r << 16) | (unsigned)d;
        }
    }
    __syncthreads();
    int v = sdeg[t];
    soff[t] = v;
    __syncthreads();
    for (int d = 1; d < 1024; d <<= 1) {
        int cur = soff[t];
        int add = (t >= d) ? soff[t - d] : 0;
        __syncthreads();
        soff[t] = cur + add;
        __syncthreads();
    }
    int excl = soff[t] - v;
    if (t < NPER) {
        g_off[nbase + t] = ebase + excl;
        g_dis[nbase + t] = rsqrtf((float)(v + 1));
    }
    if (g == NG - 1 && t == 0) g_off[NN] = EE;
    sdeg[t] = excl;
    __syncthreads();
#pragma unroll
    for (int k = 0; k < 32; k++) {
        int e = t + (k << 10);
        if (e < EPG) {
            unsigned p = pk[k];
            int d = p & 0xFFFFu;
            int r = (int)(p >> 16);
            g_csr[ebase + sdeg[d] + r] = src[ebase + e];
        }
    }
}

// ============ GEMM1: xw = x @ W1 (no dis -> independent of build) ============
__global__ void k_gemm1(const float* __restrict__ x, const float* __restrict__ W1) {
    __shared__ float xs[64 * 129];
    __shared__ float ws[128 * 16];
    int tid = threadIdx.x;
    int v0 = blockIdx.x * 64;
    for (int i = tid; i < 2048; i += 256) ws[i] = W1[i];
    const float4* x4 = (const float4*)x;
    for (int i = tid; i < 64 * 32; i += 256) {
        int r = i >> 5, c = i & 31;
        int v = v0 + r;
        float4 val = (v < NN) ? x4[(size_t)v * 32 + c] : make_float4(0.f, 0.f, 0.f, 0.f);
        float* p = &xs[r * 129 + c * 4];
        p[0] = val.x; p[1] = val.y; p[2] = val.z; p[3] = val.w;
    }
    __syncthreads();
    int n = tid & 63;
    int jg = tid >> 6;
    float4 acc = make_float4(0.f, 0.f, 0.f, 0.f);
    const float4* ws4 = (const float4*)ws;
    const float* xr = &xs[n * 129];
#pragma unroll 8
    for (int k = 0; k < 128; k++) {
        float xv = xr[k];
        float4 w = ws4[k * 4 + jg];
        acc.x += xv * w.x; acc.y += xv * w.y; acc.z += xv * w.z; acc.w += xv * w.w;
    }
    int v = v0 + n;
    if (v < NN) g_xw[v * 4 + jg] = acc;
}

// ============ conv1: scalar 16-lane SMEM gather; tile = xw*dis at load ============
__global__ void __launch_bounds__(512) k_conv1(const float* __restrict__ b1,
                                               const float* __restrict__ wrel,
                                               const float* __restrict__ wroot) {
    extern __shared__ float tile[];   // [1000][16] = xw * dis
    int g = blockIdx.x >> 2;
    int quarter = blockIdx.x & 3;
    int nbase = g * NPER;
    int tid = threadIdx.x;
    const float4* src4 = (const float4*)&g_xw[nbase * 4];
    float4* t4 = (float4*)tile;
    for (int i = tid; i < NPER * 4; i += 512) {
        int vl = i >> 2;
        float d = g_dis[nbase + vl];
        float4 val = src4[i];
        t4[i] = make_float4(val.x * d, val.y * d, val.z * d, val.w * d);
    }
    __syncthreads();
    int wid = tid >> 5, lane = tid & 31;
    int hh = lane >> 4, f = lane & 15;
    float bf = __ldg(&b1[f]);
    float wrf = __ldg(&wrel[f]);
    float wof = __ldg(&wroot[f]);
    int vbeg = quarter * 250, vend = vbeg + 250;
    for (int vl = vbeg + wid; vl < vend; vl += 16) {
        int v = nbase + vl;
        int beg = g_off[v], end = g_off[v + 1];
        float acc = 0.f;
        for (int i = beg + hh; i < end; i += 2) {
            int u = __ldg(&g_csr[i]) - nbase;
            acc += tile[u * 16 + f];
        }
        acc += __shfl_xor_sync(0xffffffffu, acc, 16);
        float d = g_dis[v];
        float hv = fmaxf(fmaf(d, acc + tile[vl * 16 + f], bf), 0.f);
        if (hh == 0) ((float*)g_h4)[v * 16 + f] = hv;
        float pp = hv * wrf;
        float rr = hv * wof;
#pragma unroll
        for (int m = 1; m < 16; m <<= 1) {
            pp += __shfl_xor_sync(0xffffffffu, pp, m);
            rr += __shfl_xor_sync(0xffffffffu, rr, m);
        }
        if (lane == 0) { g_p[v] = pp; g_hr[v] = rr; }
    }
}

// ============ topk: score (thread-per-node, p-tile SMEM) + hybrid bitonic + deg2 =====
__global__ void __launch_bounds__(1024) k_topk(const float* __restrict__ brel) {
    __shared__ unsigned long long keys[1024];
    __shared__ float p_s[NPER];
    __shared__ float smask[NPER];
    int g = blockIdx.x, t = threadIdx.x;
    int nbase = g * NPER;

    if (t < NPER) p_s[t] = g_p[nbase + t];
    __syncthreads();

    // ---- score: thread t owns node t ----
    float sc = 0.f;
    if (t < NPER) {
        int v = nbase + t;
        float s = gather_sum_smem(p_s, g_off[v], g_off[v + 1], nbase);
        sc = tanhf(s + g_hr[v] + __ldg(brel));
        unsigned u = __float_as_uint(sc);
        u = (u & 0x80000000u) ? ~u : (u | 0x80000000u);   // monotone float map
        keys[t] = ((unsigned long long)u << 32) | (unsigned)(~t);  // ties: lower idx wins
    } else {
        keys[t] = 0ull;
    }
    __syncthreads();

    // ---- hybrid bitonic sort (smem j>=32, shfl j<32) ----
    for (int k = 2; k <= 1024; k <<= 1) {
        for (int j = k >> 1; j >= 32; j >>= 1) {
            int ixj = t ^ j;
            if (ixj > t) {
                unsigned long long a = keys[t], b = keys[ixj];
                bool up = ((t & k) == 0);
                if ((a > b) == up) { keys[t] = b; keys[ixj] = a; }
            }
            __syncthreads();
        }
        unsigned long long v = keys[t];
        bool up = ((t & k) == 0);
        int jstart = (k >> 1 < 16) ? (k >> 1) : 16;
        for (int j = jstart; j > 0; j >>= 1) {
            unsigned long long o = __shfl_xor_sync(0xffffffffu, v, j);
            bool lower = ((t & j) == 0);
            bool keepmin = (lower == up);
            unsigned long long mn = (v < o) ? v : o;
            unsigned long long mx = (v < o) ? o : v;
            v = keepmin ? mn : mx;
        }
        keys[t] = v;
        __syncthreads();
    }
    if (t >= (1024 - NPER)) {
        unsigned idx = ~(unsigned)(keys[t] & 0xFFFFFFFFull);
        smask[idx] = (t >= 1024 - KTOP) ? 1.0f : 0.0f;
    }
    __syncthreads();

    // ---- deg2 / dis2; f = score*dis2 (score still in register) ----
    if (t < NPER) {
        int v = nbase + t;
        float s = gather_sum_smem(smask, g_off[v], g_off[v + 1], nbase);
        float mv = smask[t];
        float d2 = (mv > 0.f) ? rsqrtf(mv + s) : 0.f;
        g_dis2[v] = d2;
        g_f[v] = sc * d2;
    }
}

// ============ conv2: 64KB c2-tile (3 blocks/SM), float4 gather ============
__global__ void __launch_bounds__(512) k_conv2() {
    extern __shared__ float c2[];   // [1000*16]
    int g = blockIdx.x >> 2;
    int quarter = blockIdx.x & 3;
    int nbase = g * NPER;
    int t = threadIdx.x;
    const float4* h4 = (const float4*)&g_h4[nbase * 4];
    float4* c24 = (float4*)c2;
    for (int i = t; i < NPER * 4; i += 512) {
        int vl = i >> 2;
        float f = __ldg(&g_f[nbase + vl]);
        float4 h = h4[i];
        c24[i] = make_float4(h.x * f, h.y * f, h.z * f, h.w * f);
    }
    __syncthreads();
    int wid = t >> 5, lane = t & 31;
    int sub = lane >> 2, c = lane & 3;
    int vbeg = quarter * 250, vend = vbeg + 250;
    for (int vl = vbeg + wid; vl < vend; vl += 16) {
        int v = nbase + vl;
        float d2 = g_dis2[v];
        if (d2 == 0.f) continue;
        int beg = g_off[v], end = g_off[v + 1];
        float4 acc = make_float4(0.f, 0.f, 0.f, 0.f);
        for (int i = beg + sub; i < end; i += 8) {
            int u = __ldg(&g_csr[i]) - nbase;
            float4 tt = c24[u * 4 + c];
            acc.x += tt.x; acc.y += tt.y; acc.z += tt.z; acc.w += tt.w;
        }
#pragma unroll
        for (int m = 4; m < 32; m <<= 1) {
            acc.x += __shfl_xor_sync(0xffffffffu, acc.x, m);
            acc.y += __shfl_xor_sync(0xffffffffu, acc.y, m);
            acc.z += __shfl_xor_sync(0xffffffffu, acc.z, m);
            acc.w += __shfl_xor_sync(0xffffffffu, acc.w, m);
        }
        if (sub == 0) {
            float4 cv = c24[vl * 4 + c];
            g_gg[v * 4 + c] = make_float4(d2 * (acc.x + cv.x), d2 * (acc.y + cv.y),
                                          d2 * (acc.z + cv.z), d2 * (acc.w + cv.w));
        }
    }
}

// ============ fused GEMM2(16->256) + relu + masked mean pool (W2 in regs) ============
__global__ void k_pool(const float* __restrict__ W2, const float* __restrict__ b2,
                       float* __restrict__ out) {
    __shared__ float gs[16][16];
    __shared__ float ms[16];
    int t = threadIdx.x;
    int gi = blockIdx.x >> 3;
    int part = blockIdx.x & 7;
    int node0 = gi * NPER + part * 125;
    float w0[16], w1[16];
#pragma unroll
    for (int m = 0; m < 16; m++) {
        w0[m] = __ldg(&W2[m * 256 + t]);
        w1[m] = __ldg(&W2[m * 256 + t + 128]);
    }
    float bb0 = __ldg(&b2[t]), bb1 = __ldg(&b2[t + 128]);
    float acc0 = 0.f, acc1 = 0.f;
    const float* gflat = (const float*)g_gg;
    for (int base = 0; base < 125; base += 16) {
        int ns = min(16, 125 - base);
        for (int i = t; i < ns * 16; i += 128)
            ((float*)gs)[i] = gflat[(node0 + base) * 16 + i];
        if (t < ns) ms[t] = g_dis2[node0 + base + t];
        __syncthreads();
        for (int q = 0; q < ns; q++) {
            if (ms[q] != 0.f) {
                float s0 = bb0, s1 = bb1;
#pragma unroll
                for (int m = 0; m < 16; m++) {
                    float gv = gs[q][m];
                    s0 = fmaf(gv, w0[m], s0);
                    s1 = fmaf(gv, w1[m], s1);
                }
                acc0 += fmaxf(s0, 0.f);
                acc1 += fmaxf(s1, 0.f);
            }
        }
        __syncthreads();
    }
    const float inv = 1.0f / (float)KTOP;
    atomicAdd(&out[gi * 256 + t], acc0 * inv);
    atomicAdd(&out[gi * 256 + t + 128], acc1 * inv);
}

// ============ launch: fork build || gemm1, join before conv1 ============
extern "C" void kernel_launch(void* const* d_in, const int* in_sizes, int n_in,
                              void* d_out, int out_size) {
    const float* x     = (const float*)d_in[0];
    const int*   ei    = (const int*)d_in[1];
    const float* W1    = (const float*)d_in[3];
    const float* b1    = (const float*)d_in[4];
    const float* wrel  = (const float*)d_in[5];
    const float* brel  = (const float*)d_in[6];
    const float* wroot = (const float*)d_in[7];
    const float* W2    = (const float*)d_in[8];
    const float* b2    = (const float*)d_in[9];
    float* out = (float*)d_out;

    const int* src = ei;
    const int* dst = ei + EE;

    static cudaStream_t s2 = nullptr;
    static cudaEvent_t eFork = nullptr, eJoin = nullptr;
    if (s2 == nullptr) {
        cudaStreamCreateWithFlags(&s2, cudaStreamNonBlocking);
        cudaEventCreateWithFlags(&eFork, cudaEventDisableTiming);
        cudaEventCreateWithFlags(&eJoin, cudaEventDisableTiming);
        const int TILE_SMEM = NPER * 16 * 4;   // 64000
        cudaFuncSetAttribute(k_conv1, cudaFuncAttributeMaxDynamicSharedMemorySize, TILE_SMEM);
        cudaFuncSetAttribute(k_conv2, cudaFuncAttributeMaxDynamicSharedMemorySize, TILE_SMEM);
    }
    const int TILE_SMEM = NPER * 16 * 4;

    cudaMemsetAsync(d_out, 0, (size_t)out_size * sizeof(float), 0);

    // fork: gemm1 on s2 runs concurrently with build on the main stream
    cudaEventRecord(eFork, 0);
    cudaStreamWaitEvent(s2, eFork, 0);
    k_gemm1<<<(NN + 63) / 64, 256, 0, s2>>>(x, W1);
    cudaEventRecord(eJoin, s2);

    k_build<<<NG, 1024>>>(src, dst);

    // join: conv1 needs both csr/dis (build) and xw (gemm1)
    cudaStreamWaitEvent(0, eJoin, 0);

    k_conv1<<<NG * 4, 512, TILE_SMEM>>>(b1, wrel, wroot);
    k_topk<<<NG, 1024>>>(brel);
    k_conv2<<<NG * 4, 512, TILE_SMEM>>>();
    k_pool<<<NG * 8, 128>>>(W2, b2, out);
}

// round 17
// speedup vs baseline: 1.0799x; 1.0347x over previous
#include <cuda_runtime.h>

#define NN 100000
#define EE 3200000
#define NG 100
#define NPER 1000
#define EPG 32000
#define KTOP 800

// ---------------- global scratch (static; no cudaMalloc) ----------------
__device__ int    g_off[NN + 1];
__device__ int    g_csr[EE];
__device__ float  g_dis[NN];
__device__ float  g_dis2[NN];
__device__ float  g_f[NN];             // score * dis2 (0 for masked)
__device__ float  g_p[NN];             // h . w_rel
__device__ float  g_hr[NN];            // h . w_root
__device__ float4 g_xw[NN * 4];        // x @ W1 (NO dis) [N,16]
__device__ float4 g_h4[NN * 4];        // conv1 output  [N,16]
__device__ float4 g_gg[NN * 4];        // conv2 agg (pre-W2) [N,16]

// ---- thread-per-node scalar gather over one CSR bucket, table in SMEM ----
__device__ __forceinline__ float gather_sum_smem(const float* __restrict__ tab,
                                                 int beg, int end, int nbase) {
    float a0 = 0.f, a1 = 0.f, a2 = 0.f, a3 = 0.f;
    int i = beg;
    for (; i < end && (i & 3); i++) a0 += tab[__ldg(&g_csr[i]) - nbase];
    int n4 = (end - i) >> 2;
    const int4* c4 = (const int4*)&g_csr[i];
    for (int k = 0; k < n4; k++) {
        int4 u = __ldg(&c4[k]);
        a0 += tab[u.x - nbase];
        a1 += tab[u.y - nbase];
        a2 += tab[u.z - nbase];
        a3 += tab[u.w - nbase];
    }
    for (i += n4 << 2; i < end; i++) a0 += tab[__ldg(&g_csr[i]) - nbase];
    return (a0 + a1) + (a2 + a3);
}

// ============ CSR build: register-cached ranks (no g_rank round-trip) ============
__global__ void __launch_bounds__(1024) k_build(const int* __restrict__ src,
                                                const int* __restrict__ dst) {
    __shared__ int sdeg[1024];
    __shared__ int soff[1024];
    int g = blockIdx.x, t = threadIdx.x;
    int ebase = g * EPG, nbase = g * NPER;
    sdeg[t] = 0;
    __syncthreads();
    unsigned pk[32];   // (rank<<16) | local_dst
#pragma unroll
    for (int k = 0; k < 32; k++) {
        int e = t + (k << 10);
        if (e < EPG) {
            int d = dst[ebase + e] - nbase;
            unsigned r = atomicAdd(&sdeg[d], 1);
            pk[k] = (r << 16) | (unsigned)d;
        }
    }
    __syncthreads();
    int v = sdeg[t];
    soff[t] = v;
    __syncthreads();
    for (int d = 1; d < 1024; d <<= 1) {
        int cur = soff[t];
        int add = (t >= d) ? soff[t - d] : 0;
        __syncthreads();
        soff[t] = cur + add;
        __syncthreads();
    }
    int excl = soff[t] - v;
    if (t < NPER) {
        g_off[nbase + t] = ebase + excl;
        g_dis[nbase + t] = rsqrtf((float)(v + 1));
    }
    if (g == NG - 1 && t == 0) g_off[NN] = EE;
    sdeg[t] = excl;
    __syncthreads();
#pragma unroll
    for (int k = 0; k < 32; k++) {
        int e = t + (k << 10);
        if (e < EPG) {
            unsigned p = pk[k];
            int d = p & 0xFFFFu;
            int r = (int)(p >> 16);
            g_csr[ebase + sdeg[d] + r] = src[ebase + e];
        }
    }
}

// ============ GEMM1: xw = x @ W1 (no dis -> independent of build) ============
__global__ void k_gemm1(const float* __restrict__ x, const float* __restrict__ W1) {
    __shared__ float xs[64 * 129];
    __shared__ float ws[128 * 16];
    int tid = threadIdx.x;
    int v0 = blockIdx.x * 64;
    for (int i = tid; i < 2048; i += 256) ws[i] = W1[i];
    const float4* x4 = (const float4*)x;
    for (int i = tid; i < 64 * 32; i += 256) {
        int r = i >> 5, c = i & 31;
        int v = v0 + r;
        float4 val = (v < NN) ? x4[(size_t)v * 32 + c] : make_float4(0.f, 0.f, 0.f, 0.f);
        float* p = &xs[r * 129 + c * 4];
        p[0] = val.x; p[1] = val.y; p[2] = val.z; p[3] = val.w;
    }
    __syncthreads();
    int n = tid & 63;
    int jg = tid >> 6;
    float4 acc = make_float4(0.f, 0.f, 0.f, 0.f);
    const float4* ws4 = (const float4*)ws;
    const float* xr = &xs[n * 129];
#pragma unroll 8
    for (int k = 0; k < 128; k++) {
        float xv = xr[k];
        float4 w = ws4[k * 4 + jg];
        acc.x += xv * w.x; acc.y += xv * w.y; acc.z += xv * w.z; acc.w += xv * w.w;
    }
    int v = v0 + n;
    if (v < NN) g_xw[v * 4 + jg] = acc;
}

// ============ conv1: scalar 16-lane SMEM gather; tile = xw*dis at load ============
__global__ void __launch_bounds__(512) k_conv1(const float* __restrict__ b1,
                                               const float* __restrict__ wrel,
                                               const float* __restrict__ wroot) {
    extern __shared__ float tile[];   // [1000][16] = xw * dis
    int g = blockIdx.x >> 2;
    int quarter = blockIdx.x & 3;
    int nbase = g * NPER;
    int tid = threadIdx.x;
    const float4* src4 = (const float4*)&g_xw[nbase * 4];
    float4* t4 = (float4*)tile;
    for (int i = tid; i < NPER * 4; i += 512) {
        int vl = i >> 2;
        float d = g_dis[nbase + vl];
        float4 val = src4[i];
        t4[i] = make_float4(val.x * d, val.y * d, val.z * d, val.w * d);
    }
    __syncthreads();
    int wid = tid >> 5, lane = tid & 31;
    int hh = lane >> 4, f = lane & 15;
    float bf = __ldg(&b1[f]);
    float wrf = __ldg(&wrel[f]);
    float wof = __ldg(&wroot[f]);
    int vbeg = quarter * 250, vend = vbeg + 250;
    for (int vl = vbeg + wid; vl < vend; vl += 16) {
        int v = nbase + vl;
        int beg = g_off[v], end = g_off[v + 1];
        float acc = 0.f;
        for (int i = beg + hh; i < end; i += 2) {
            int u = __ldg(&g_csr[i]) - nbase;
            acc += tile[u * 16 + f];
        }
        acc += __shfl_xor_sync(0xffffffffu, acc, 16);
        float d = g_dis[v];
        float hv = fmaxf(fmaf(d, acc + tile[vl * 16 + f], bf), 0.f);
        if (hh == 0) ((float*)g_h4)[v * 16 + f] = hv;
        float pp = hv * wrf;
        float rr = hv * wof;
#pragma unroll
        for (int m = 1; m < 16; m <<= 1) {
            pp += __shfl_xor_sync(0xffffffffu, pp, m);
            rr += __shfl_xor_sync(0xffffffffu, rr, m);
        }
        if (lane == 0) { g_p[v] = pp; g_hr[v] = rr; }
    }
}

// ============ topk: score + MSD radix-select (rank KTOP) + deg2, fused ============
__global__ void __launch_bounds__(1024) k_topk(const float* __restrict__ brel) {
    __shared__ float p_s[NPER];
    __shared__ float smask[NPER];
    __shared__ int hist[256];
    __shared__ int sh_D, sh_want, sh_done;
    int g = blockIdx.x, t = threadIdx.x;
    int nbase = g * NPER;

    if (t < NPER) p_s[t] = g_p[nbase + t];
    if (t == 0) { sh_want = KTOP; sh_done = 0; }
    __syncthreads();

    // ---- score: thread t owns node t; build 64-bit selection key ----
    float sc = 0.f;
    unsigned long long key = 0ull;
    if (t < NPER) {
        int v = nbase + t;
        float s = gather_sum_smem(p_s, g_off[v], g_off[v + 1], nbase);
        sc = tanhf(s + g_hr[v] + __ldg(brel));
        unsigned u = __float_as_uint(sc);
        u = (u & 0x80000000u) ? ~u : (u | 0x80000000u);   // monotone float map
        key = ((unsigned long long)u << 32) | (unsigned)(~t);  // ties: lower idx wins
    }

    // ---- MSD radix select: find the KTOP largest keys (exact, unique keys) ----
    int state = 0;   // 0 = active, 1 = selected, 2 = rejected
    for (int shift = 56; shift >= 0; shift -= 8) {
        if (t < 256) hist[t] = 0;
        __syncthreads();
        int dig = -1;
        if (t < NPER && state == 0) {
            dig = (int)((key >> shift) & 0xFFull);
            atomicAdd(&hist[dig], 1);
        }
        __syncthreads();
        if (t < 32) {
            int want = sh_want;
            int base = t * 8;
            int h[8];
            int s8 = 0;
#pragma unroll
            for (int i = 0; i < 8; i++) { h[i] = hist[base + i]; s8 += h[i]; }
            // inclusive suffix scan of s8 across lanes (sum over [lane..31])
            int x = s8;
#pragma unroll
            for (int off = 1; off < 32; off <<= 1) {
                int y = __shfl_down_sync(0xffffffffu, x, off);
                if (t + off < 32) x += y;
            }
            int suf = x - s8;                 // exclusive suffix (lanes > t)
            if (suf < want && suf + s8 >= want) {
                int cg = suf, D = -1, hD = 0;
#pragma unroll
                for (int i = 7; i >= 0; i--) {
                    if (cg + h[i] >= want) { D = base + i; hD = h[i]; break; }
                    cg += h[i];
                }
                sh_D = D;
                int wantp = want - cg;        // still needed from bin D
                sh_want = wantp;
                sh_done = (hD == wantp) ? 1 : 0;
            }
        }
        __syncthreads();
        int D = sh_D;
        int done = sh_done;
        if (state == 0 && dig >= 0) {
            if (dig > D) state = 1;
            else if (dig < D) state = 2;
            else if (done) state = 1;         // whole boundary bin selected
        }
        __syncthreads();
        if (done) break;                      // uniform (read after barrier)
    }
    if (t < NPER) smask[t] = (state == 1) ? 1.0f : 0.0f;
    __syncthreads();

    // ---- deg2 / dis2; f = score*dis2 (score still in register) ----
    if (t < NPER) {
        int v = nbase + t;
        float s = gather_sum_smem(smask, g_off[v], g_off[v + 1], nbase);
        float mv = smask[t];
        float d2 = (mv > 0.f) ? rsqrtf(mv + s) : 0.f;
        g_dis2[v] = d2;
        g_f[v] = sc * d2;
    }
}

// ============ conv2: 64KB c2-tile (3 blocks/SM), float4 gather ============
__global__ void __launch_bounds__(512) k_conv2() {
    extern __shared__ float c2[];   // [1000*16]
    int g = blockIdx.x >> 2;
    int quarter = blockIdx.x & 3;
    int nbase = g * NPER;
    int t = threadIdx.x;
    const float4* h4 = (const float4*)&g_h4[nbase * 4];
    float4* c24 = (float4*)c2;
    for (int i = t; i < NPER * 4; i += 512) {
        int vl = i >> 2;
        float f = __ldg(&g_f[nbase + vl]);
        float4 h = h4[i];
        c24[i] = make_float4(h.x * f, h.y * f, h.z * f, h.w * f);
    }
    __syncthreads();
    int wid = t >> 5, lane = t & 31;
    int sub = lane >> 2, c = lane & 3;
    int vbeg = quarter * 250, vend = vbeg + 250;
    for (int vl = vbeg + wid; vl < vend; vl += 16) {
        int v = nbase + vl;
        float d2 = g_dis2[v];
        if (d2 == 0.f) continue;
        int beg = g_off[v], end = g_off[v + 1];
        float4 acc = make_float4(0.f, 0.f, 0.f, 0.f);
        for (int i = beg + sub; i < end; i += 8) {
            int u = __ldg(&g_csr[i]) - nbase;
            float4 tt = c24[u * 4 + c];
            acc.x += tt.x; acc.y += tt.y; acc.z += tt.z; acc.w += tt.w;
        }
#pragma unroll
        for (int m = 4; m < 32; m <<= 1) {
            acc.x += __shfl_xor_sync(0xffffffffu, acc.x, m);
            acc.y += __shfl_xor_sync(0xffffffffu, acc.y, m);
            acc.z += __shfl_xor_sync(0xffffffffu, acc.z, m);
            acc.w += __shfl_xor_sync(0xffffffffu, acc.w, m);
        }
        if (sub == 0) {
            float4 cv = c24[vl * 4 + c];
            g_gg[v * 4 + c] = make_float4(d2 * (acc.x + cv.x), d2 * (acc.y + cv.y),
                                          d2 * (acc.z + cv.z), d2 * (acc.w + cv.w));
        }
    }
}

// ============ fused GEMM2(16->256) + relu + masked mean pool (W2 in regs) ============
__global__ void k_pool(const float* __restrict__ W2, const float* __restrict__ b2,
                       float* __restrict__ out) {
    __shared__ float gs[16][16];
    __shared__ float ms[16];
    int t = threadIdx.x;
    int gi = blockIdx.x >> 3;
    int part = blockIdx.x & 7;
    int node0 = gi * NPER + part * 125;
    float w0[16], w1[16];
#pragma unroll
    for (int m = 0; m < 16; m++) {
        w0[m] = __ldg(&W2[m * 256 + t]);
        w1[m] = __ldg(&W2[m * 256 + t + 128]);
    }
    float bb0 = __ldg(&b2[t]), bb1 = __ldg(&b2[t + 128]);
    float acc0 = 0.f, acc1 = 0.f;
    const float* gflat = (const float*)g_gg;
    for (int base = 0; base < 125; base += 16) {
        int ns = min(16, 125 - base);
        for (int i = t; i < ns * 16; i += 128)
            ((float*)gs)[i] = gflat[(node0 + base) * 16 + i];
        if (t < ns) ms[t] = g_dis2[node0 + base + t];
        __syncthreads();
        for (int q = 0; q < ns; q++) {
            if (ms[q] != 0.f) {
                float s0 = bb0, s1 = bb1;
#pragma unroll
                for (int m = 0; m < 16; m++) {
                    float gv = gs[q][m];
                    s0 = fmaf(gv, w0[m], s0);
                    s1 = fmaf(gv, w1[m], s1);
                }
                acc0 += fmaxf(s0, 0.f);
                acc1 += fmaxf(s1, 0.f);
            }
        }
        __syncthreads();
    }
    const float inv = 1.0f / (float)KTOP;
    atomicAdd(&out[gi * 256 + t], acc0 * inv);
    atomicAdd(&out[gi * 256 + t + 128], acc1 * inv);
}

// ============ launch: fork build || gemm1, join before conv1 ============
extern "C" void kernel_launch(void* const* d_in, const int* in_sizes, int n_in,
                              void* d_out, int out_size) {
    const float* x     = (const float*)d_in[0];
    const int*   ei    = (const int*)d_in[1];
    const float* W1    = (const float*)d_in[3];
    const float* b1    = (const float*)d_in[4];
    const float* wrel  = (const float*)d_in[5];
    const float* brel  = (const float*)d_in[6];
    const float* wroot = (const float*)d_in[7];
    const float* W2    = (const float*)d_in[8];
    const float* b2    = (const float*)d_in[9];
    float* out = (float*)d_out;

    const int* src = ei;
    const int* dst = ei + EE;

    static cudaStream_t s2 = nullptr;
    static cudaEvent_t eFork = nullptr, eJoin = nullptr;
    if (s2 == nullptr) {
        cudaStreamCreateWithFlags(&s2, cudaStreamNonBlocking);
        cudaEventCreateWithFlags(&eFork, cudaEventDisableTiming);
        cudaEventCreateWithFlags(&eJoin, cudaEventDisableTiming);
        const int TILE_SMEM = NPER * 16 * 4;   // 64000
        cudaFuncSetAttribute(k_conv1, cudaFuncAttributeMaxDynamicSharedMemorySize, TILE_SMEM);
        cudaFuncSetAttribute(k_conv2, cudaFuncAttributeMaxDynamicSharedMemorySize, TILE_SMEM);
    }
    const int TILE_SMEM = NPER * 16 * 4;

    cudaMemsetAsync(d_out, 0, (size_t)out_size * sizeof(float), 0);

    // fork: gemm1 on s2 runs concurrently with build on the main stream
    cudaEventRecord(eFork, 0);
    cudaStreamWaitEvent(s2, eFork, 0);
    k_gemm1<<<(NN + 63) / 64, 256, 0, s2>>>(x, W1);
    cudaEventRecord(eJoin, s2);

    k_build<<<NG, 1024>>>(src, dst);

    // join: conv1 needs both csr/dis (build) and xw (gemm1)
    cudaStreamWaitEvent(0, eJoin, 0);

    k_conv1<<<NG * 4, 512, TILE_SMEM>>>(b1, wrel, wroot);
    k_topk<<<NG, 1024>>>(brel);
    k_conv2<<<NG * 4, 512, TILE_SMEM>>>();
    k_pool<<<NG * 8, 128>>>(W2, b2, out);
}